// round 11
// baseline (speedup 1.0000x reference)
#include <cuda_runtime.h>
#include <cuda_bf16.h>
#include <cstdint>
#include <math.h>

#define N_SPK 1024
#define M_UTT 20
#define D_DIM 768
#define NM    (N_SPK * M_UTT)   // 20480

// ---- scratch (static device globals; no allocation in kernel_launch) ----
__device__ __nv_bfloat16 g_e[(size_t)NM * D_DIM];      // normalized e, row r = m*N + i
__device__ __nv_bfloat16 g_c[(size_t)N_SPK * D_DIM];   // normalized centroids
__device__ float         g_expsum[NM];                 // per-logit-row sum of exp
__device__ float         g_tgt[NM];                    // per-logit-row target logit
__device__ double        g_acc;                        // logp accumulator
__device__ int           g_cnt[160];                   // per-(m, jb) arrival counters (self-reset)
__device__ int           g_done;                       // group completion counter (self-reset)

// =================================================================== PTX utils
__device__ __forceinline__ uint32_t smem_u32(const void* p) {
    uint32_t a;
    asm("{ .reg .u64 t; cvta.to.shared.u64 t, %1; cvt.u32.u64 %0, t; }" : "=r"(a) : "l"(p));
    return a;
}
__device__ __forceinline__ void cp16(uint32_t saddr, const void* gptr) {
    asm volatile("cp.async.cg.shared.global [%0], [%1], 16;" :: "r"(saddr), "l"(gptr));
}
__device__ __forceinline__ void cp_commit() {
    asm volatile("cp.async.commit_group;" ::: "memory");
}
template <int N>
__device__ __forceinline__ void cp_wait() {
    asm volatile("cp.async.wait_group %0;" :: "n"(N) : "memory");
}
__device__ __forceinline__ void ldsm_x4(uint32_t& r0, uint32_t& r1, uint32_t& r2, uint32_t& r3,
                                        uint32_t addr) {
    asm volatile("ldmatrix.sync.aligned.m8n8.x4.shared.b16 {%0,%1,%2,%3}, [%4];"
                 : "=r"(r0), "=r"(r1), "=r"(r2), "=r"(r3) : "r"(addr));
}
__device__ __forceinline__ void mma16816(float* d, const uint32_t* a, const uint32_t* b) {
    asm volatile(
        "mma.sync.aligned.m16n8k16.row.col.f32.bf16.bf16.f32 "
        "{%0,%1,%2,%3}, {%4,%5,%6,%7}, {%8,%9}, {%0,%1,%2,%3};"
        : "+f"(d[0]), "+f"(d[1]), "+f"(d[2]), "+f"(d[3])
        : "r"(a[0]), "r"(a[1]), "r"(a[2]), "r"(a[3]), "r"(b[0]), "r"(b[1]));
}

// ---------------------------------------------------------------- reductions
__device__ __forceinline__ float block_reduce_sum(float v, float* red) {
    int t = threadIdx.x;
    #pragma unroll
    for (int o = 16; o; o >>= 1) v += __shfl_down_sync(0xffffffffu, v, o);
    if ((t & 31) == 0) red[t >> 5] = v;
    __syncthreads();
    if (t < 32) {
        float x = (t < (int)(blockDim.x >> 5)) ? red[t] : 0.0f;
        #pragma unroll
        for (int o = 16; o; o >>= 1) x += __shfl_down_sync(0xffffffffu, x, o);
        if (t == 0) red[0] = x;
    }
    __syncthreads();
    float r = red[0];
    __syncthreads();
    return r;
}

// ---------------------------------------------- fused normalize + centroid
// 1024 blocks (speaker i) x 768 threads. Warps 0-19 own utterances; also
// zeroes this speaker's 20 g_expsum slots and (block 0) g_acc.
#define NC_SMEM (M_UTT * D_DIM * 4 + 128)

__global__ void __launch_bounds__(768, 2) normcent_kernel(const float* __restrict__ emb) {
    extern __shared__ __align__(16) char nsm[];
    float* cent_s = reinterpret_cast<float*>(nsm);                  // [20][768]
    float* red    = reinterpret_cast<float*>(nsm + M_UTT * D_DIM * 4);

    const int i    = blockIdx.x;
    const int t    = threadIdx.x;
    const int wid  = t >> 5;
    const int lane = t & 31;

    if (t < M_UTT) g_expsum[i * M_UTT + t] = 0.0f;
    if (i == 0 && t == 0) g_acc = 0.0;

    if (wid < M_UTT) {
        const int m = wid;
        const float* src = emb + ((size_t)i * M_UTT + m) * D_DIM;
        float4 v[6];
        float ss = 0.0f;
        #pragma unroll
        for (int q = 0; q < 6; q++) {
            v[q] = *reinterpret_cast<const float4*>(src + lane * 4 + q * 128);
            ss += v[q].x * v[q].x + v[q].y * v[q].y + v[q].z * v[q].z + v[q].w * v[q].w;
        }
        #pragma unroll
        for (int o = 16; o; o >>= 1) ss += __shfl_xor_sync(0xffffffffu, ss, o);
        float inv = 1.0f / fmaxf(sqrtf(ss), 1e-8f);

        __nv_bfloat16* dst = g_e + (size_t)(m * N_SPK + i) * D_DIM;
        #pragma unroll
        for (int q = 0; q < 6; q++) {
            int off = lane * 4 + q * 128;
            *reinterpret_cast<float4*>(cent_s + m * D_DIM + off) = v[q];
            __nv_bfloat162 lo = __floats2bfloat162_rn(v[q].x * inv, v[q].y * inv);
            __nv_bfloat162 hi = __floats2bfloat162_rn(v[q].z * inv, v[q].w * inv);
            *reinterpret_cast<__nv_bfloat162*>(dst + off)     = lo;
            *reinterpret_cast<__nv_bfloat162*>(dst + off + 2) = hi;
        }
    }
    __syncthreads();

    // phase 2: thread t owns dim t
    float ds = 0.0f;
    #pragma unroll
    for (int m = 0; m < M_UTT; m++) ds += cent_s[m * D_DIM + t];
    ds *= (1.0f / M_UTT);
    cent_s[t] = ds;
    float tot = block_reduce_sum(ds * ds, red);
    float inv = 1.0f / fmaxf(sqrtf(tot), 1e-8f);
    if (t < D_DIM / 2) {
        __nv_bfloat162 p = __floats2bfloat162_rn(cent_s[2 * t] * inv, cent_s[2 * t + 1] * inv);
        *reinterpret_cast<__nv_bfloat162*>(g_c + (size_t)i * D_DIM + 2 * t) = p;
    }
}

// ------------------------------------------------------------ mma.sync GEMM
// Persistent: 296 CTAs, static tiles (c, c+296, ...), cp.async chunk stream
// runs continuously ACROSS tile boundaries (one cold fill per CTA).
// CTA tile 128x128, BK=64, 4 warps (2m x 2n), warp tile 64x64, XOR-8 swizzle,
// 3 rotating 32KB stages, 2 CTAs/SM. Fused softmax epilogue + last-CTA loss.
#define BK        64
#define NKC       (D_DIM / BK)          // 12
#define A_BYTES   (128 * 128)           // 16 KB
#define STAGE_B   (2 * A_BYTES)         // 32 KB (A + B)
#define NSTAGE    3
#define SMEM_GEMM (NSTAGE * STAGE_B)    // 96 KB
#define NCTA      296
#define NTILE     (NM / 128 * (N_SPK / 128))   // 160 x 8 = 1280

__device__ __forceinline__ void load_chunk_t(uint32_t stage_base, int tile, int kc, int tid) {
    const int jb = (tile / 160) * 128;
    const int nb = (tile % 160) * 128;
    const int k0 = kc * BK;
    uint32_t base = stage_base;
    #pragma unroll
    for (int q = 0; q < 8; q++) {
        int idx = tid + q * 128;        // 0..1023
        int r = idx >> 3, c = idx & 7;
        cp16(base + r * 128 + ((c ^ (r & 7)) << 4),
             g_c + (size_t)(jb + r) * D_DIM + k0 + c * 8);
    }
    base += A_BYTES;
    #pragma unroll
    for (int q = 0; q < 8; q++) {
        int idx = tid + q * 128;
        int r = idx >> 3, c = idx & 7;
        cp16(base + r * 128 + ((c ^ (r & 7)) << 4),
             g_e + (size_t)(nb + r) * D_DIM + k0 + c * 8);
    }
}

__global__ void __launch_bounds__(128, 2)
gemm_mma_kernel(const float* __restrict__ wp, const float* __restrict__ bp,
                float* __restrict__ out) {
    extern __shared__ __align__(1024) char smc[];
    __shared__ int   sh_is_last;
    __shared__ float sh_red[4];
    uint32_t sb = smem_u32(smc);
    const int tid  = threadIdx.x;
    const int lane = tid & 31;
    const int wid  = tid >> 5;
    const int wm   = wid & 1;           // 2 warps along m (64 rows each)
    const int wn   = wid >> 1;          // 2 warps along n (64 cols each)

    const int sw    = lane & 7;
    const int a_row0 = wm * 64 + (lane & 15);                      // + mf*16
    const int a_hi  = lane >> 4;
    const int b_row0 = wn * 64 + (lane & 7) + ((lane >> 4) << 3);  // + nfp*16
    const int b_hi  = (lane >> 3) & 1;

    const float wv = *wp, bv = *bp;

    int tile    = blockIdx.x;           // current tile
    int pre_tile = tile, pre_kc = 0;    // next chunk to prefetch
    int q_w = 0;                        // chunks issued (stage = q_w % 3)

    // cold fill: 2 chunks
    #pragma unroll
    for (int p = 0; p < 2; p++) {
        load_chunk_t(sb + (q_w % NSTAGE) * STAGE_B, pre_tile, pre_kc, tid);
        cp_commit(); q_w++;
        if (++pre_kc == NKC) { pre_kc = 0; pre_tile += NCTA; }
    }

    int q_r = 0;                        // chunks consumed
    #pragma unroll 1
    while (tile < NTILE) {
        float acc[4][8][4];
        #pragma unroll
        for (int mf = 0; mf < 4; mf++)
            #pragma unroll
            for (int nf = 0; nf < 8; nf++)
                #pragma unroll
                for (int q = 0; q < 4; q++) acc[mf][nf][q] = 0.0f;

        #pragma unroll 1
        for (int kc = 0; kc < NKC; kc++) {
            if (tile + NCTA >= NTILE && kc == NKC - 1) cp_wait<0>(); else cp_wait<1>();
            __syncthreads();
            if (pre_tile < NTILE) {
                load_chunk_t(sb + (q_w % NSTAGE) * STAGE_B, pre_tile, pre_kc, tid);
                cp_commit(); q_w++;
                if (++pre_kc == NKC) { pre_kc = 0; pre_tile += NCTA; }
            }
            uint32_t Ab = sb + (q_r % NSTAGE) * STAGE_B;
            uint32_t Bb = Ab + A_BYTES;
            q_r++;
            #pragma unroll
            for (int ks = 0; ks < 4; ks++) {
                uint32_t a[4][4];
                #pragma unroll
                for (int mf = 0; mf < 4; mf++) {
                    uint32_t addr = Ab + (a_row0 + mf * 16) * 128 + (((ks * 2 + a_hi) ^ sw) << 4);
                    ldsm_x4(a[mf][0], a[mf][1], a[mf][2], a[mf][3], addr);
                }
                #pragma unroll
                for (int nfp = 0; nfp < 4; nfp++) {
                    uint32_t b4[4];
                    uint32_t addr = Bb + (b_row0 + nfp * 16) * 128 + (((ks * 2 + b_hi) ^ sw) << 4);
                    ldsm_x4(b4[0], b4[1], b4[2], b4[3], addr);
                    #pragma unroll
                    for (int mf = 0; mf < 4; mf++) {
                        mma16816(acc[mf][2 * nfp + 0], a[mf], b4 + 0);
                        mma16816(acc[mf][2 * nfp + 1], a[mf], b4 + 2);
                    }
                }
            }
        }

        // ---------------- fused softmax epilogue ----------------
        const int jb    = (tile / 160) * 128;
        const int nb    = (tile % 160) * 128;
        const int m_idx = nb >> 10;
        const int i0    = nb & 1023;

        #pragma unroll
        for (int mf = 0; mf < 4; mf++) {
            float p0 = 0.0f, p1 = 0.0f;
            #pragma unroll
            for (int nf = 0; nf < 8; nf++) {
                p0 += __expf(fmaf(wv, acc[mf][nf][0], bv)) + __expf(fmaf(wv, acc[mf][nf][1], bv));
                p1 += __expf(fmaf(wv, acc[mf][nf][2], bv)) + __expf(fmaf(wv, acc[mf][nf][3], bv));
            }
            p0 += __shfl_xor_sync(0xffffffffu, p0, 1);
            p0 += __shfl_xor_sync(0xffffffffu, p0, 2);
            p1 += __shfl_xor_sync(0xffffffffu, p1, 1);
            p1 += __shfl_xor_sync(0xffffffffu, p1, 2);
            int j0 = jb + wm * 64 + mf * 16 + (lane >> 2);   // half 0; half 1 is +8
            if ((lane & 3) == 0) {
                atomicAdd(&g_expsum[m_idx * N_SPK + j0],     p0);
                atomicAdd(&g_expsum[m_idx * N_SPK + j0 + 8], p1);
            }
            #pragma unroll
            for (int half = 0; half < 2; half++) {
                int j = j0 + half * 8;
                int r = m_idx * N_SPK + j;
                int c = r / M_UTT - i0;
                if (c >= 0 && c < 128 && (c >> 6) == wn && ((c & 7) >> 1) == (lane & 3)) {
                    int tnf = (c & 63) >> 3;
                    #pragma unroll
                    for (int nf = 0; nf < 8; nf++) {
                        if (nf == tnf) {
                            float v = (c & 1) ? acc[mf][nf][half * 2 + 1]
                                              : acc[mf][nf][half * 2 + 0];
                            g_tgt[r] = fmaf(wv, v, bv);
                        }
                    }
                }
            }
        }

        // ---------------- last-CTA loss finalize ----------------
        __threadfence();
        __syncthreads();
        const int grp = m_idx * 8 + (jb >> 7);
        if (tid == 0) {
            int old = atomicAdd(&g_cnt[grp], 1);
            sh_is_last = (old == 7);
        }
        __syncthreads();
        if (sh_is_last) {
            __threadfence();
            int r = m_idx * N_SPK + jb + tid;    // 128 threads -> 128 rows
            float v = g_tgt[r] - __logf(g_expsum[r]);
            #pragma unroll
            for (int o = 16; o; o >>= 1) v += __shfl_down_sync(0xffffffffu, v, o);
            if (lane == 0) sh_red[wid] = v;
            __syncthreads();
            if (tid == 0) {
                g_cnt[grp] = 0;              // self-reset for graph replay
                float s = sh_red[0] + sh_red[1] + sh_red[2] + sh_red[3];
                atomicAdd(&g_acc, (double)s);
                __threadfence();
                int old = atomicAdd(&g_done, 1);
                if (old == 159) {
                    double tot = atomicAdd(&g_acc, 0.0);
                    out[0] = (float)(-tot / (double)NM);
                    g_done = 0;              // self-reset for graph replay
                }
            }
        }
        __syncthreads();                     // sh_is_last/sh_red reuse safety
        tile += NCTA;
    }
}

// ---------------------------------------------------------------- launch
extern "C" void kernel_launch(void* const* d_in, const int* in_sizes, int n_in,
                              void* d_out, int out_size) {
    const float* emb = (const float*)d_in[0];
    const float* w   = (const float*)d_in[1];
    const float* b   = (const float*)d_in[2];
    float* out = (float*)d_out;

    static int smem_set = 0;
    if (!smem_set) {
        cudaFuncSetAttribute(gemm_mma_kernel, cudaFuncAttributeMaxDynamicSharedMemorySize,
                             SMEM_GEMM);
        cudaFuncSetAttribute(normcent_kernel, cudaFuncAttributeMaxDynamicSharedMemorySize,
                             NC_SMEM);
        smem_set = 1;
    }

    normcent_kernel<<<N_SPK, 768, NC_SMEM>>>(emb);
    gemm_mma_kernel<<<NCTA, 128, SMEM_GEMM>>>(w, b, out);
}

// round 12
// speedup vs baseline: 1.0389x; 1.0389x over previous
#include <cuda_runtime.h>
#include <cuda_bf16.h>
#include <cstdint>
#include <math.h>

#define N_SPK 1024
#define M_UTT 20
#define D_DIM 768
#define NM    (N_SPK * M_UTT)   // 20480

// ---- scratch (static device globals; no allocation in kernel_launch) ----
__device__ __nv_bfloat16 g_e[(size_t)NM * D_DIM];      // normalized e, row r = m*N + i
__device__ __nv_bfloat16 g_c[(size_t)N_SPK * D_DIM];   // normalized centroids
__device__ float         g_expsum[NM];                 // per-logit-row sum of exp
__device__ float         g_tgt[NM];                    // per-logit-row target logit
__device__ double        g_acc;                        // logp accumulator
__device__ int           g_cnt[160];                   // per-(m, jb) arrival counters (self-reset)
__device__ int           g_done;                       // group completion counter (self-reset)

// =================================================================== PTX utils
__device__ __forceinline__ uint32_t smem_u32(const void* p) {
    uint32_t a;
    asm("{ .reg .u64 t; cvta.to.shared.u64 t, %1; cvt.u32.u64 %0, t; }" : "=r"(a) : "l"(p));
    return a;
}
__device__ __forceinline__ void cp16(uint32_t saddr, const void* gptr) {
    asm volatile("cp.async.cg.shared.global [%0], [%1], 16;" :: "r"(saddr), "l"(gptr));
}
__device__ __forceinline__ void cp_commit() {
    asm volatile("cp.async.commit_group;" ::: "memory");
}
template <int N>
__device__ __forceinline__ void cp_wait() {
    asm volatile("cp.async.wait_group %0;" :: "n"(N) : "memory");
}
__device__ __forceinline__ void ldsm_x4(uint32_t& r0, uint32_t& r1, uint32_t& r2, uint32_t& r3,
                                        uint32_t addr) {
    asm volatile("ldmatrix.sync.aligned.m8n8.x4.shared.b16 {%0,%1,%2,%3}, [%4];"
                 : "=r"(r0), "=r"(r1), "=r"(r2), "=r"(r3) : "r"(addr));
}
__device__ __forceinline__ void mma16816(float* d, const uint32_t* a, const uint32_t* b) {
    asm volatile(
        "mma.sync.aligned.m16n8k16.row.col.f32.bf16.bf16.f32 "
        "{%0,%1,%2,%3}, {%4,%5,%6,%7}, {%8,%9}, {%0,%1,%2,%3};"
        : "+f"(d[0]), "+f"(d[1]), "+f"(d[2]), "+f"(d[3])
        : "r"(a[0]), "r"(a[1]), "r"(a[2]), "r"(a[3]), "r"(b[0]), "r"(b[1]));
}

// ---------------------------------------------- fused normalize + centroid
// 1024 blocks (speaker i) x 640 threads (20 warps, one per utterance).
// Streaming: load float4 -> stage to smem -> accumulate ss (low regs, 3 blocks/SM).
// Phase 2: thread t owns dims t and t+640. Also zeroes expsum slots / g_acc.
#define NC_SMEM (M_UTT * D_DIM * 4 + 128)   // 61440 stage + red

__global__ void __launch_bounds__(640, 3) normcent_kernel(const float* __restrict__ emb) {
    extern __shared__ __align__(16) char nsm[];
    float* stage = reinterpret_cast<float*>(nsm);                   // [20][768]
    float* red   = reinterpret_cast<float*>(nsm + M_UTT * D_DIM * 4);

    const int i    = blockIdx.x;
    const int t    = threadIdx.x;
    const int m    = t >> 5;            // warp id == utterance
    const int lane = t & 31;

    if (t < M_UTT) g_expsum[i * M_UTT + t] = 0.0f;
    if (i == 0 && t == 0) g_acc = 0.0;

    // phase 1: warp m loads+stages its utterance row, computes norm, writes bf16
    {
        const float* src = emb + ((size_t)i * M_UTT + m) * D_DIM;
        float* dstS = stage + m * D_DIM;
        float ss = 0.0f;
        #pragma unroll
        for (int q = 0; q < 6; q++) {
            int off = lane * 4 + q * 128;
            float4 v = *reinterpret_cast<const float4*>(src + off);
            *reinterpret_cast<float4*>(dstS + off) = v;
            ss += v.x * v.x + v.y * v.y + v.z * v.z + v.w * v.w;
        }
        #pragma unroll
        for (int o = 16; o; o >>= 1) ss += __shfl_xor_sync(0xffffffffu, ss, o);
        float inv = 1.0f / fmaxf(sqrtf(ss), 1e-8f);

        __nv_bfloat16* dst = g_e + (size_t)(m * N_SPK + i) * D_DIM;
        #pragma unroll
        for (int q = 0; q < 6; q++) {
            int off = lane * 4 + q * 128;
            float4 v = *reinterpret_cast<const float4*>(dstS + off);
            __nv_bfloat162 lo = __floats2bfloat162_rn(v.x * inv, v.y * inv);
            __nv_bfloat162 hi = __floats2bfloat162_rn(v.z * inv, v.w * inv);
            *reinterpret_cast<__nv_bfloat162*>(dst + off)     = lo;
            *reinterpret_cast<__nv_bfloat162*>(dst + off + 2) = hi;
        }
    }
    __syncthreads();

    // phase 2: centroid; thread t owns dim t (and t+640 if t<128)
    float ds0 = 0.0f, ds1 = 0.0f;
    const int d1 = t + 640;
    #pragma unroll
    for (int mm = 0; mm < M_UTT; mm++) {
        ds0 += stage[mm * D_DIM + t];
        if (t < 128) ds1 += stage[mm * D_DIM + d1];
    }
    ds0 *= (1.0f / M_UTT);
    ds1 *= (1.0f / M_UTT);
    float part = ds0 * ds0 + ((t < 128) ? ds1 * ds1 : 0.0f);

    // block reduce (20 warps)
    #pragma unroll
    for (int o = 16; o; o >>= 1) part += __shfl_down_sync(0xffffffffu, part, o);
    if (lane == 0) red[m] = part;
    __syncthreads();
    if (t < 32) {
        float x = (t < M_UTT) ? red[t] : 0.0f;
        #pragma unroll
        for (int o = 16; o; o >>= 1) x += __shfl_down_sync(0xffffffffu, x, o);
        if (t == 0) red[0] = x;
    }
    __syncthreads();
    float inv = 1.0f / fmaxf(sqrtf(red[0]), 1e-8f);

    g_c[(size_t)i * D_DIM + t] = __float2bfloat16(ds0 * inv);
    if (t < 128) g_c[(size_t)i * D_DIM + d1] = __float2bfloat16(ds1 * inv);
}

// ------------------------------------------------------------ mma.sync GEMM
// S = C (1024x768) * E^T (768x20480). CTA 128x128, BK=64, 4 warps (2m x 2n),
// warp tile 64x64. 128B smem rows, XOR-8 swizzle, 3-stage cp.async pipeline,
// 2 CTAs/SM. Epilogue folds softmax partials; the last CTA per (m, jb) group
// finalizes its 128 logit rows; the globally-last group writes the loss.
#define BK        64
#define NKC       (D_DIM / BK)          // 12
#define A_BYTES   (128 * 128)           // 16 KB
#define STAGE_B   (2 * A_BYTES)         // 32 KB (A + B)
#define NSTAGE    3
#define SMEM_GEMM (NSTAGE * STAGE_B)    // 96 KB

__device__ __forceinline__ void load_chunk(uint32_t sb, int st, int kc, int jb, int nb, int tid) {
    uint32_t base = sb + st * STAGE_B;
    const int k0 = kc * BK;
    #pragma unroll
    for (int q = 0; q < 8; q++) {
        int idx = tid + q * 128;        // 0..1023
        int r = idx >> 3, c = idx & 7;
        cp16(base + r * 128 + ((c ^ (r & 7)) << 4),
             g_c + (size_t)(jb + r) * D_DIM + k0 + c * 8);
    }
    base += A_BYTES;
    #pragma unroll
    for (int q = 0; q < 8; q++) {
        int idx = tid + q * 128;
        int r = idx >> 3, c = idx & 7;
        cp16(base + r * 128 + ((c ^ (r & 7)) << 4),
             g_e + (size_t)(nb + r) * D_DIM + k0 + c * 8);
    }
}

__global__ void __launch_bounds__(128, 2)
gemm_mma_kernel(const float* __restrict__ wp, const float* __restrict__ bp,
                float* __restrict__ out) {
    extern __shared__ __align__(1024) char smc[];
    __shared__ int   sh_is_last;
    __shared__ float sh_red[4];
    uint32_t sb = smem_u32(smc);
    const int tid  = threadIdx.x;
    const int lane = tid & 31;
    const int wid  = tid >> 5;
    const int wm   = wid & 1;           // 2 warps along m (64 rows each)
    const int wn   = wid >> 1;          // 2 warps along n (64 cols each)
    const int jb   = blockIdx.y * 128;
    const int nb   = blockIdx.x * 128;

    float acc[4][8][4];
    #pragma unroll
    for (int mf = 0; mf < 4; mf++)
        #pragma unroll
        for (int nf = 0; nf < 8; nf++)
            #pragma unroll
            for (int q = 0; q < 4; q++) acc[mf][nf][q] = 0.0f;

    const int sw    = lane & 7;
    const int a_row = wm * 64 + (lane & 15);                       // + mf*16
    const int a_hi  = lane >> 4;
    const int b_row = wn * 64 + (lane & 7) + ((lane >> 4) << 3);   // + nfp*16
    const int b_hi  = (lane >> 3) & 1;

    load_chunk(sb, 0, 0, jb, nb, tid); cp_commit();
    load_chunk(sb, 1, 1, jb, nb, tid); cp_commit();

    #pragma unroll 1
    for (int kc = 0; kc < NKC; kc++) {
        if (kc == NKC - 1) cp_wait<0>(); else cp_wait<1>();
        __syncthreads();
        if (kc + 2 < NKC) {
            load_chunk(sb, (kc + 2) % NSTAGE, kc + 2, jb, nb, tid);
            cp_commit();
        }
        uint32_t Ab = sb + (kc % NSTAGE) * STAGE_B;
        uint32_t Bb = Ab + A_BYTES;
        #pragma unroll
        for (int ks = 0; ks < 4; ks++) {
            uint32_t a[4][4];
            #pragma unroll
            for (int mf = 0; mf < 4; mf++) {
                uint32_t addr = Ab + (a_row + mf * 16) * 128 + (((ks * 2 + a_hi) ^ sw) << 4);
                ldsm_x4(a[mf][0], a[mf][1], a[mf][2], a[mf][3], addr);
            }
            #pragma unroll
            for (int nfp = 0; nfp < 4; nfp++) {
                uint32_t b4[4];
                uint32_t addr = Bb + (b_row + nfp * 16) * 128 + (((ks * 2 + b_hi) ^ sw) << 4);
                ldsm_x4(b4[0], b4[1], b4[2], b4[3], addr);
                #pragma unroll
                for (int mf = 0; mf < 4; mf++) {
                    mma16816(acc[mf][2 * nfp + 0], a[mf], b4 + 0);
                    mma16816(acc[mf][2 * nfp + 1], a[mf], b4 + 2);
                }
            }
        }
    }

    // ---------------- fused softmax epilogue ----------------
    // rows j in [jb, jb+128), cols (m, i): m = nb/1024, i in [i0, i0+128).
    const float wv = *wp, bv = *bp;
    const int m_idx = nb >> 10;
    const int i0    = nb & 1023;

    #pragma unroll
    for (int mf = 0; mf < 4; mf++) {
        float p0 = 0.0f, p1 = 0.0f;
        #pragma unroll
        for (int nf = 0; nf < 8; nf++) {
            p0 += __expf(fmaf(wv, acc[mf][nf][0], bv)) + __expf(fmaf(wv, acc[mf][nf][1], bv));
            p1 += __expf(fmaf(wv, acc[mf][nf][2], bv)) + __expf(fmaf(wv, acc[mf][nf][3], bv));
        }
        p0 += __shfl_xor_sync(0xffffffffu, p0, 1);
        p0 += __shfl_xor_sync(0xffffffffu, p0, 2);
        p1 += __shfl_xor_sync(0xffffffffu, p1, 1);
        p1 += __shfl_xor_sync(0xffffffffu, p1, 2);
        int j0 = jb + wm * 64 + mf * 16 + (lane >> 2);   // half 0; half 1 is +8
        if ((lane & 3) == 0) {
            atomicAdd(&g_expsum[m_idx * N_SPK + j0],     p0);
            atomicAdd(&g_expsum[m_idx * N_SPK + j0 + 8], p1);
        }
        // target logit: row r's target col is i* = r / M_UTT
        #pragma unroll
        for (int half = 0; half < 2; half++) {
            int j = j0 + half * 8;
            int r = m_idx * N_SPK + j;
            int c = r / M_UTT - i0;
            if (c >= 0 && c < 128 && (c >> 6) == wn && ((c & 7) >> 1) == (lane & 3)) {
                int tnf = (c & 63) >> 3;
                #pragma unroll
                for (int nf = 0; nf < 8; nf++) {
                    if (nf == tnf) {
                        float v = (c & 1) ? acc[mf][nf][half * 2 + 1]
                                          : acc[mf][nf][half * 2 + 0];
                        g_tgt[r] = fmaf(wv, v, bv);
                    }
                }
            }
        }
    }

    // ---------------- last-CTA loss finalize ----------------
    __threadfence();                     // publish expsum atomics + tgt stores
    __syncthreads();
    const int grp = m_idx * 8 + (jb >> 7);
    if (tid == 0) {
        int old = atomicAdd(&g_cnt[grp], 1);
        sh_is_last = (old == 7);
    }
    __syncthreads();
    if (sh_is_last) {
        __threadfence();                 // acquire side
        int r = m_idx * N_SPK + jb + tid;    // 128 threads -> 128 rows
        float v = g_tgt[r] - __logf(g_expsum[r]);
        #pragma unroll
        for (int o = 16; o; o >>= 1) v += __shfl_down_sync(0xffffffffu, v, o);
        if (lane == 0) sh_red[wid] = v;
        __syncthreads();
        if (tid == 0) {
            g_cnt[grp] = 0;              // self-reset for graph replay
            float s = sh_red[0] + sh_red[1] + sh_red[2] + sh_red[3];
            atomicAdd(&g_acc, (double)s);
            __threadfence();
            int old = atomicAdd(&g_done, 1);
            if (old == 159) {
                double tot = atomicAdd(&g_acc, 0.0);
                out[0] = (float)(-tot / (double)NM);
                g_done = 0;              // self-reset for graph replay
            }
        }
    }
}

// ---------------------------------------------------------------- launch
extern "C" void kernel_launch(void* const* d_in, const int* in_sizes, int n_in,
                              void* d_out, int out_size) {
    const float* emb = (const float*)d_in[0];
    const float* w   = (const float*)d_in[1];
    const float* b   = (const float*)d_in[2];
    float* out = (float*)d_out;

    static int smem_set = 0;
    if (!smem_set) {
        cudaFuncSetAttribute(gemm_mma_kernel, cudaFuncAttributeMaxDynamicSharedMemorySize,
                             SMEM_GEMM);
        cudaFuncSetAttribute(normcent_kernel, cudaFuncAttributeMaxDynamicSharedMemorySize,
                             NC_SMEM);
        smem_set = 1;
    }

    normcent_kernel<<<N_SPK, 640, NC_SMEM>>>(emb);
    dim3 ggrid(NM / 128, N_SPK / 128);   // 160 x 8
    gemm_mma_kernel<<<ggrid, 128, SMEM_GEMM>>>(w, b, out);
}

// round 13
// speedup vs baseline: 1.1019x; 1.0606x over previous
#include <cuda_runtime.h>
#include <cuda_bf16.h>
#include <cstdint>
#include <math.h>

#define N_SPK 1024
#define M_UTT 20
#define D_DIM 768
#define NM    (N_SPK * M_UTT)   // 20480

// ---- scratch (static device globals; no allocation in kernel_launch) ----
__device__ __nv_bfloat16 g_e[(size_t)NM * D_DIM];      // normalized e, row r = m*N + i
__device__ __nv_bfloat16 g_c[(size_t)N_SPK * D_DIM];   // normalized centroids
__device__ float         g_expsum[NM];                 // per-logit-row sum of exp
__device__ float         g_tgt[NM];                    // per-logit-row target logit
__device__ double        g_acc;                        // logp accumulator
__device__ int           g_cnt[160];                   // per-(m, jb) arrival counters (self-reset)
__device__ int           g_done;                       // group completion counter (self-reset)

// =================================================================== PTX utils
__device__ __forceinline__ uint32_t smem_u32(const void* p) {
    uint32_t a;
    asm("{ .reg .u64 t; cvta.to.shared.u64 t, %1; cvt.u32.u64 %0, t; }" : "=r"(a) : "l"(p));
    return a;
}
__device__ __forceinline__ void cp16(uint32_t saddr, const void* gptr) {
    asm volatile("cp.async.cg.shared.global [%0], [%1], 16;" :: "r"(saddr), "l"(gptr));
}
__device__ __forceinline__ void cp_commit() {
    asm volatile("cp.async.commit_group;" ::: "memory");
}
template <int N>
__device__ __forceinline__ void cp_wait() {
    asm volatile("cp.async.wait_group %0;" :: "n"(N) : "memory");
}
__device__ __forceinline__ void ldsm_x4(uint32_t& r0, uint32_t& r1, uint32_t& r2, uint32_t& r3,
                                        uint32_t addr) {
    asm volatile("ldmatrix.sync.aligned.m8n8.x4.shared.b16 {%0,%1,%2,%3}, [%4];"
                 : "=r"(r0), "=r"(r1), "=r"(r2), "=r"(r3) : "r"(addr));
}
__device__ __forceinline__ void mma16816(float* d, const uint32_t* a, const uint32_t* b) {
    asm volatile(
        "mma.sync.aligned.m16n8k16.row.col.f32.bf16.bf16.f32 "
        "{%0,%1,%2,%3}, {%4,%5,%6,%7}, {%8,%9}, {%0,%1,%2,%3};"
        : "+f"(d[0]), "+f"(d[1]), "+f"(d[2]), "+f"(d[3])
        : "r"(a[0]), "r"(a[1]), "r"(a[2]), "r"(a[3]), "r"(b[0]), "r"(b[1]));
}

// ---------------------------------------------------------------- reductions
__device__ __forceinline__ float block_reduce_sum(float v, float* red) {
    int t = threadIdx.x;
    #pragma unroll
    for (int o = 16; o; o >>= 1) v += __shfl_down_sync(0xffffffffu, v, o);
    if ((t & 31) == 0) red[t >> 5] = v;
    __syncthreads();
    if (t < 32) {
        float x = (t < (int)(blockDim.x >> 5)) ? red[t] : 0.0f;
        #pragma unroll
        for (int o = 16; o; o >>= 1) x += __shfl_down_sync(0xffffffffu, x, o);
        if (t == 0) red[0] = x;
    }
    __syncthreads();
    float r = red[0];
    __syncthreads();
    return r;
}

// ---------------------------------------------- fused normalize + centroid
// 1024 blocks (speaker i) x 768 threads. Warps 0-19 own utterances; also
// zeroes this speaker's 20 g_expsum slots and (block 0) g_acc.  (R10 proven)
#define NC_SMEM (M_UTT * D_DIM * 4 + 128)

__global__ void __launch_bounds__(768, 2) normcent_kernel(const float* __restrict__ emb) {
    extern __shared__ __align__(16) char nsm[];
    float* cent_s = reinterpret_cast<float*>(nsm);                  // [20][768]
    float* red    = reinterpret_cast<float*>(nsm + M_UTT * D_DIM * 4);

    const int i    = blockIdx.x;
    const int t    = threadIdx.x;
    const int wid  = t >> 5;
    const int lane = t & 31;

    if (t < M_UTT) g_expsum[i * M_UTT + t] = 0.0f;
    if (i == 0 && t == 0) g_acc = 0.0;

    if (wid < M_UTT) {
        const int m = wid;
        const float* src = emb + ((size_t)i * M_UTT + m) * D_DIM;
        float4 v[6];
        float ss = 0.0f;
        #pragma unroll
        for (int q = 0; q < 6; q++) {
            v[q] = *reinterpret_cast<const float4*>(src + lane * 4 + q * 128);
            ss += v[q].x * v[q].x + v[q].y * v[q].y + v[q].z * v[q].z + v[q].w * v[q].w;
        }
        #pragma unroll
        for (int o = 16; o; o >>= 1) ss += __shfl_xor_sync(0xffffffffu, ss, o);
        float inv = 1.0f / fmaxf(sqrtf(ss), 1e-8f);

        __nv_bfloat16* dst = g_e + (size_t)(m * N_SPK + i) * D_DIM;
        #pragma unroll
        for (int q = 0; q < 6; q++) {
            int off = lane * 4 + q * 128;
            *reinterpret_cast<float4*>(cent_s + m * D_DIM + off) = v[q];
            __nv_bfloat162 lo = __floats2bfloat162_rn(v[q].x * inv, v[q].y * inv);
            __nv_bfloat162 hi = __floats2bfloat162_rn(v[q].z * inv, v[q].w * inv);
            *reinterpret_cast<__nv_bfloat162*>(dst + off)     = lo;
            *reinterpret_cast<__nv_bfloat162*>(dst + off + 2) = hi;
        }
    }
    __syncthreads();

    // phase 2: thread t owns dim t
    float ds = 0.0f;
    #pragma unroll
    for (int m = 0; m < M_UTT; m++) ds += cent_s[m * D_DIM + t];
    ds *= (1.0f / M_UTT);
    cent_s[t] = ds;
    float tot = block_reduce_sum(ds * ds, red);
    float inv = 1.0f / fmaxf(sqrtf(tot), 1e-8f);
    if (t < D_DIM / 2) {
        __nv_bfloat162 p = __floats2bfloat162_rn(cent_s[2 * t] * inv, cent_s[2 * t + 1] * inv);
        *reinterpret_cast<__nv_bfloat162*>(g_c + (size_t)i * D_DIM + 2 * t) = p;
    }
}

// ------------------------------------------------------------ mma.sync GEMM
// S = C (1024x768) * E^T (768x20480). CTA 128x128, BK=64, 4 warps (2m x 2n),
// warp tile 64x64. 128B smem rows, XOR-8 swizzle, 3-stage cp.async pipeline,
// 2 CTAs/SM. Per-ks: ALL 8 LDSMs issued up-front (A+B fragment hoist), then
// 32 dependency-free MMAs. Fused softmax epilogue + last-CTA loss finalize.
#define BK        64
#define NKC       (D_DIM / BK)          // 12
#define A_BYTES   (128 * 128)           // 16 KB
#define STAGE_B   (2 * A_BYTES)         // 32 KB (A + B)
#define NSTAGE    3
#define SMEM_GEMM (NSTAGE * STAGE_B)    // 96 KB

__device__ __forceinline__ void load_chunk(uint32_t sb, int st, int kc, int jb, int nb, int tid) {
    uint32_t base = sb + st * STAGE_B;
    const int k0 = kc * BK;
    #pragma unroll
    for (int q = 0; q < 8; q++) {
        int idx = tid + q * 128;        // 0..1023
        int r = idx >> 3, c = idx & 7;
        cp16(base + r * 128 + ((c ^ (r & 7)) << 4),
             g_c + (size_t)(jb + r) * D_DIM + k0 + c * 8);
    }
    base += A_BYTES;
    #pragma unroll
    for (int q = 0; q < 8; q++) {
        int idx = tid + q * 128;
        int r = idx >> 3, c = idx & 7;
        cp16(base + r * 128 + ((c ^ (r & 7)) << 4),
             g_e + (size_t)(nb + r) * D_DIM + k0 + c * 8);
    }
}

__global__ void __launch_bounds__(128, 2)
gemm_mma_kernel(const float* __restrict__ wp, const float* __restrict__ bp,
                float* __restrict__ out) {
    extern __shared__ __align__(1024) char smc[];
    __shared__ int   sh_is_last;
    __shared__ float sh_red[4];
    uint32_t sb = smem_u32(smc);
    const int tid  = threadIdx.x;
    const int lane = tid & 31;
    const int wid  = tid >> 5;
    const int wm   = wid & 1;           // 2 warps along m (64 rows each)
    const int wn   = wid >> 1;          // 2 warps along n (64 cols each)
    const int jb   = blockIdx.y * 128;
    const int nb   = blockIdx.x * 128;

    float acc[4][8][4];
    #pragma unroll
    for (int mf = 0; mf < 4; mf++)
        #pragma unroll
        for (int nf = 0; nf < 8; nf++)
            #pragma unroll
            for (int q = 0; q < 4; q++) acc[mf][nf][q] = 0.0f;

    const int sw    = lane & 7;
    const int a_row = wm * 64 + (lane & 15);                       // + mf*16
    const int a_hi  = lane >> 4;
    const int b_row = wn * 64 + (lane & 7) + ((lane >> 4) << 3);   // + nfp*16
    const int b_hi  = (lane >> 3) & 1;

    load_chunk(sb, 0, 0, jb, nb, tid); cp_commit();
    load_chunk(sb, 1, 1, jb, nb, tid); cp_commit();

    #pragma unroll 1
    for (int kc = 0; kc < NKC; kc++) {
        if (kc == NKC - 1) cp_wait<0>(); else cp_wait<1>();
        __syncthreads();
        if (kc + 2 < NKC) {
            load_chunk(sb, (kc + 2) % NSTAGE, kc + 2, jb, nb, tid);
            cp_commit();
        }
        uint32_t Ab = sb + (kc % NSTAGE) * STAGE_B;
        uint32_t Bb = Ab + A_BYTES;
        #pragma unroll
        for (int ks = 0; ks < 4; ks++) {
            // hoist: issue all 8 LDSMs back-to-back, then 32 dependency-free MMAs
            uint32_t b4[4][4];
            #pragma unroll
            for (int nfp = 0; nfp < 4; nfp++) {
                uint32_t addr = Bb + (b_row + nfp * 16) * 128 + (((ks * 2 + b_hi) ^ sw) << 4);
                ldsm_x4(b4[nfp][0], b4[nfp][1], b4[nfp][2], b4[nfp][3], addr);
            }
            uint32_t a[4][4];
            #pragma unroll
            for (int mf = 0; mf < 4; mf++) {
                uint32_t addr = Ab + (a_row + mf * 16) * 128 + (((ks * 2 + a_hi) ^ sw) << 4);
                ldsm_x4(a[mf][0], a[mf][1], a[mf][2], a[mf][3], addr);
            }
            #pragma unroll
            for (int nfp = 0; nfp < 4; nfp++) {
                #pragma unroll
                for (int mf = 0; mf < 4; mf++) {
                    mma16816(acc[mf][2 * nfp + 0], a[mf], b4[nfp] + 0);
                    mma16816(acc[mf][2 * nfp + 1], a[mf], b4[nfp] + 2);
                }
            }
        }
    }

    // ---------------- fused softmax epilogue ----------------
    // rows j in [jb, jb+128), cols (m, i): m = nb/1024, i in [i0, i0+128).
    const float wv = *wp, bv = *bp;
    const int m_idx = nb >> 10;
    const int i0    = nb & 1023;

    #pragma unroll
    for (int mf = 0; mf < 4; mf++) {
        float p0 = 0.0f, p1 = 0.0f;
        #pragma unroll
        for (int nf = 0; nf < 8; nf++) {
            p0 += __expf(fmaf(wv, acc[mf][nf][0], bv)) + __expf(fmaf(wv, acc[mf][nf][1], bv));
            p1 += __expf(fmaf(wv, acc[mf][nf][2], bv)) + __expf(fmaf(wv, acc[mf][nf][3], bv));
        }
        p0 += __shfl_xor_sync(0xffffffffu, p0, 1);
        p0 += __shfl_xor_sync(0xffffffffu, p0, 2);
        p1 += __shfl_xor_sync(0xffffffffu, p1, 1);
        p1 += __shfl_xor_sync(0xffffffffu, p1, 2);
        int j0 = jb + wm * 64 + mf * 16 + (lane >> 2);   // half 0; half 1 is +8
        if ((lane & 3) == 0) {
            atomicAdd(&g_expsum[m_idx * N_SPK + j0],     p0);
            atomicAdd(&g_expsum[m_idx * N_SPK + j0 + 8], p1);
        }
        // target logit: row r's target col is i* = r / M_UTT
        #pragma unroll
        for (int half = 0; half < 2; half++) {
            int j = j0 + half * 8;
            int r = m_idx * N_SPK + j;
            int c = r / M_UTT - i0;
            if (c >= 0 && c < 128 && (c >> 6) == wn && ((c & 7) >> 1) == (lane & 3)) {
                int tnf = (c & 63) >> 3;
                #pragma unroll
                for (int nf = 0; nf < 8; nf++) {
                    if (nf == tnf) {
                        float v = (c & 1) ? acc[mf][nf][half * 2 + 1]
                                          : acc[mf][nf][half * 2 + 0];
                        g_tgt[r] = fmaf(wv, v, bv);
                    }
                }
            }
        }
    }

    // ---------------- last-CTA loss finalize ----------------
    __threadfence();                     // publish expsum atomics + tgt stores
    __syncthreads();
    const int grp = m_idx * 8 + (jb >> 7);
    if (tid == 0) {
        int old = atomicAdd(&g_cnt[grp], 1);
        sh_is_last = (old == 7);
    }
    __syncthreads();
    if (sh_is_last) {
        __threadfence();                 // acquire side
        int r = m_idx * N_SPK + jb + tid;    // 128 threads -> 128 rows
        float v = g_tgt[r] - __logf(g_expsum[r]);
        #pragma unroll
        for (int o = 16; o; o >>= 1) v += __shfl_down_sync(0xffffffffu, v, o);
        if (lane == 0) sh_red[wid] = v;
        __syncthreads();
        if (tid == 0) {
            g_cnt[grp] = 0;              // self-reset for graph replay
            float s = sh_red[0] + sh_red[1] + sh_red[2] + sh_red[3];
            atomicAdd(&g_acc, (double)s);
            __threadfence();
            int old = atomicAdd(&g_done, 1);
            if (old == 159) {
                double tot = atomicAdd(&g_acc, 0.0);
                out[0] = (float)(-tot / (double)NM);
                g_done = 0;              // self-reset for graph replay
            }
        }
    }
}

// ---------------------------------------------------------------- launch
extern "C" void kernel_launch(void* const* d_in, const int* in_sizes, int n_in,
                              void* d_out, int out_size) {
    const float* emb = (const float*)d_in[0];
    const float* w   = (const float*)d_in[1];
    const float* b   = (const float*)d_in[2];
    float* out = (float*)d_out;

    static int smem_set = 0;
    if (!smem_set) {
        cudaFuncSetAttribute(gemm_mma_kernel, cudaFuncAttributeMaxDynamicSharedMemorySize,
                             SMEM_GEMM);
        cudaFuncSetAttribute(normcent_kernel, cudaFuncAttributeMaxDynamicSharedMemorySize,
                             NC_SMEM);
        smem_set = 1;
    }

    normcent_kernel<<<N_SPK, 768, NC_SMEM>>>(emb);
    dim3 ggrid(NM / 128, N_SPK / 128);   // 160 x 8
    gemm_mma_kernel<<<ggrid, 128, SMEM_GEMM>>>(w, b, out);
}